// round 2
// baseline (speedup 1.0000x reference)
#include <cuda_runtime.h>
#include <cuda_bf16.h>

// AvgPool over last 4 dims of [B=2, C=16, 32,32,32,32], kernel=stride=2, pad=0.
// Output [2,16,16,16,16,16]. Each thread computes 2 adjacent outputs along d4:
// loads 8 float4 (the 2x2x2 window rows x 4 contiguous d4 inputs), writes float2.
//
// Input strides (floats): d4:1, d3:32, d2:1024, d1:32768, c:1048576
// Output linearization: ((((bc*16 + o1)*16 + o2)*16 + o3)*16 + o4)

__global__ __launch_bounds__(256, 8)
void avgpool4d_kernel(const float* __restrict__ in, float* __restrict__ out)
{
    // pair index: out_size/2 = 1,048,576 pairs
    unsigned p = blockIdx.x * 256u + threadIdx.x;

    // decompose (all powers of two -> shifts/masks)
    unsigned o4p = p & 7u;          // which pair of outputs along d4 (0..7)
    unsigned t   = p >> 3;
    unsigned o3  = t & 15u;  t >>= 4;
    unsigned o2  = t & 15u;  t >>= 4;
    unsigned o1  = t & 15u;  t >>= 4;
    unsigned bc  = t;               // 0..31

    // input base offset (floats)
    // d1 = 2*o1, d2 = 2*o2, d3 = 2*o3, d4 start = 4*o4p
    unsigned base = bc * 1048576u
                  + (o1 << 1) * 32768u
                  + (o2 << 1) * 1024u
                  + (o3 << 1) * 32u
                  + (o4p << 2);

    const float4* in4 = reinterpret_cast<const float4*>(in);
    unsigned b4 = base >> 2;        // float4 index (base is 4-aligned)

    // window row offsets in float4 units:
    // +i3*32 floats = +8 f4 ; +i2*1024 floats = +256 f4 ; +i1*32768 floats = +8192 f4
    float4 s;
    {
        float4 a0 = in4[b4          ];
        float4 a1 = in4[b4 + 8      ];
        float4 a2 = in4[b4 + 256    ];
        float4 a3 = in4[b4 + 264    ];
        float4 a4 = in4[b4 + 8192   ];
        float4 a5 = in4[b4 + 8200   ];
        float4 a6 = in4[b4 + 8448   ];
        float4 a7 = in4[b4 + 8456   ];
        s.x = (a0.x + a1.x) + (a2.x + a3.x) + ((a4.x + a5.x) + (a6.x + a7.x));
        s.y = (a0.y + a1.y) + (a2.y + a3.y) + ((a4.y + a5.y) + (a6.y + a7.y));
        s.z = (a0.z + a1.z) + (a2.z + a3.z) + ((a4.z + a5.z) + (a6.z + a7.z));
        s.w = (a0.w + a1.w) + (a2.w + a3.w) + ((a4.w + a5.w) + (a6.w + a7.w));
    }

    float2 o;
    o.x = (s.x + s.y) * 0.0625f;
    o.y = (s.z + s.w) * 0.0625f;

    reinterpret_cast<float2*>(out)[p] = o;
}

extern "C" void kernel_launch(void* const* d_in, const int* in_sizes, int n_in,
                              void* d_out, int out_size)
{
    const float* in = (const float*)d_in[0];
    float* out = (float*)d_out;
    // out_size = 2*16*16^4 = 2,097,152 ; pairs = out_size/2 ; 256 thr/block
    int pairs = out_size >> 1;
    int blocks = (pairs + 255) / 256;   // = 4096 for the reference shape
    avgpool4d_kernel<<<blocks, 256>>>(in, out);
}